// round 9
// baseline (speedup 1.0000x reference)
#include <cuda_runtime.h>
#include <mma.h>
#include <cstdint>
#include <cstddef>

using namespace nvcuda;

constexpr int S  = 10;
constexpr int D  = 512;
constexpr int NQ = 4096;
constexpr int NP = 1024;

// ------------------------- scratch (__device__ globals) ---------------------
__device__ float g_W[S * D * D];              // fp32 W [s][d][e]
__device__ float g_b[S * D];
__device__ float g_tq[(size_t)S * NQ * D];
__device__ float g_sqq[S * NQ];
__device__ float g_sqp[NP];
__device__ float g_dists[(size_t)S * NQ * NP];

// ------------------------------ Threefry-2x32 -------------------------------
__host__ __device__ __forceinline__ unsigned rotl32(unsigned x, int d) {
    return (x << d) | (x >> (32 - d));
}
__host__ __device__ __forceinline__ void tf2x32(unsigned k0, unsigned k1,
                                                unsigned &x0, unsigned &x1) {
    unsigned k2 = k0 ^ k1 ^ 0x1BD11BDAu;
    x0 += k0; x1 += k1;
#define TFR(r) { x0 += x1; x1 = rotl32(x1, r) ^ x0; }
    TFR(13) TFR(15) TFR(26) TFR(6)   x0 += k1; x1 += k2 + 1u;
    TFR(17) TFR(29) TFR(16) TFR(24)  x0 += k2; x1 += k0 + 2u;
    TFR(13) TFR(15) TFR(26) TFR(6)   x0 += k0; x1 += k1 + 3u;
    TFR(17) TFR(29) TFR(16) TFR(24)  x0 += k1; x1 += k2 + 4u;
    TFR(13) TFR(15) TFR(26) TFR(6)   x0 += k2; x1 += k0 + 5u;
#undef TFR
}
__device__ __forceinline__ unsigned jax_bits32(unsigned k0, unsigned k1, unsigned i) {
    unsigned x0 = 0u, x1 = i;
    tf2x32(k0, k1, x0, x1);
    return x0 ^ x1;
}
__device__ __forceinline__ float erfinv_xla(float x) {
    float w = -log1pf(-x * x);
    float p;
    if (w < 5.0f) {
        w -= 2.5f;
        p = 2.81022636e-08f;
        p = fmaf(p, w, 3.43273939e-07f);
        p = fmaf(p, w, -3.5233877e-06f);
        p = fmaf(p, w, -4.39150654e-06f);
        p = fmaf(p, w, 0.00021858087f);
        p = fmaf(p, w, -0.00125372503f);
        p = fmaf(p, w, -0.00417768164f);
        p = fmaf(p, w, 0.246640727f);
        p = fmaf(p, w, 1.50140941f);
    } else {
        w = sqrtf(w) - 3.0f;
        p = -0.000200214257f;
        p = fmaf(p, w, 0.000100950558f);
        p = fmaf(p, w, 0.00134934322f);
        p = fmaf(p, w, -0.00367342844f);
        p = fmaf(p, w, 0.00573950773f);
        p = fmaf(p, w, -0.0076224613f);
        p = fmaf(p, w, 0.00943887047f);
        p = fmaf(p, w, 1.00167406f);
        p = fmaf(p, w, 2.83297682f);
    }
    return p * x;
}
__device__ __forceinline__ float bits_to_normal(unsigned bits) {
    float f = __uint_as_float((bits >> 9) | 0x3F800000u) - 1.0f;
    float u = fmaxf(-0.99999994f, f * 2.0f - 0.99999994f);
    return 1.41421356237f * erfinv_xla(u);
}

// ------------------------------ prep kernels --------------------------------
__global__ void gen_w_kernel(const float* __restrict__ wmu,
                             const float* __restrict__ wrho,
                             unsigned k0, unsigned k1) {
    int i = blockIdx.x * blockDim.x + threadIdx.x;
    if (i >= S * D * D) return;
    float eps = bits_to_normal(jax_bits32(k0, k1, (unsigned)i));
    int j = i & (D * D - 1);
    g_W[i] = fmaf(log1pf(expf(wrho[j])), eps, wmu[j]);
}

__global__ void gen_b_kernel(const float* __restrict__ bmu,
                             const float* __restrict__ brho,
                             unsigned k0, unsigned k1) {
    int i = blockIdx.x * blockDim.x + threadIdx.x;
    if (i >= S * D) return;
    float eps = bits_to_normal(jax_bits32(k0, k1, (unsigned)i));
    int j = i & (D - 1);
    g_b[i] = fmaf(log1pf(expf(brho[j])), eps, bmu[j]);
}

__global__ void sqp_kernel(const float* __restrict__ P) {
    int p = blockIdx.x * 8 + (threadIdx.x >> 5);
    int lane = threadIdx.x & 31;
    const float* row = P + (size_t)p * D;
    float s = 0.f;
    for (int e = lane; e < D; e += 32) { float v = row[e]; s = fmaf(v, v, s); }
    #pragma unroll
    for (int o = 16; o; o >>= 1) s += __shfl_xor_sync(0xffffffffu, s, o);
    if (lane == 0) g_sqp[p] = s;
}

__global__ void sqq_kernel() {
    int row = blockIdx.x * 8 + (threadIdx.x >> 5);
    int lane = threadIdx.x & 31;
    const float* r = g_tq + (size_t)row * D;
    float s = 0.f;
    for (int e = lane; e < D; e += 32) { float v = r[e]; s = fmaf(v, v, s); }
    #pragma unroll
    for (int o = 16; o; o >>= 1) s += __shfl_xor_sync(0xffffffffu, s, o);
    if (lane == 0) g_sqq[row] = s;
}

// ------------------------------ async helpers --------------------------------
__device__ __forceinline__ uint32_t smem_u32(const void* p) {
    uint32_t a;
    asm("{ .reg .u64 t; cvta.to.shared.u64 t, %1; cvt.u32.u64 %0, t; }" : "=r"(a) : "l"(p));
    return a;
}
__device__ __forceinline__ void cp16(uint32_t dst, const void* src) {
    asm volatile("cp.async.cg.shared.global [%0], [%1], 16;" :: "r"(dst), "l"(src));
}
#define CP_COMMIT() asm volatile("cp.async.commit_group;" ::: "memory")
#define CP_WAIT(n)  asm volatile("cp.async.wait_group %0;" :: "n"(n) : "memory")

// in-fragment tf32 hi/lo split (verified in R8)
template <typename FragT>
__device__ __forceinline__ void split_frag(FragT& hi, FragT& lo) {
    #pragma unroll
    for (int e = 0; e < hi.num_elements; e++) {
        float v = hi.x[e];
        float h = wmma::__float_to_tf32(v);
        hi.x[e] = h;
        lo.x[e] = wmma::__float_to_tf32(v - h);
    }
}

// ---------------- GEMM1: wmma tf32x2, tq = X @ W_s + b ----------------------
// A = X [NQ,D] fp32 row-major; B = W_s [D,D] fp32 row-major (k x n).
// 128x128 tile, BK=32, 2-stage cp.async pipeline, 256 threads (8 warps 64x32).
__global__ __launch_bounds__(256, 2) void gemm_tf32_tq(const float* __restrict__ X) {
    constexpr int BK  = 32;
    constexpr int NCH = D / BK;            // 16
    constexpr int LDA = 40;                // A row stride (floats)
    constexpr int LDB = 132;               // B row stride (floats)
    constexpr int A_F = 128 * LDA;         // 5120
    constexpr int B_F = BK * LDB;          // 4224
    constexpr int STAGE = A_F + B_F;       // 9344 floats

    extern __shared__ float fsm[];
    float* aux = fsm + 2 * STAGE;          // 128 floats (bias)

    const int s  = blockIdx.z;
    const int m0 = blockIdx.y * 128;
    const int n0 = blockIdx.x * 128;
    const int tid = threadIdx.x;
    const int wid = tid >> 5, lane = tid & 31;
    const int wm  = wid & 1, wn = wid >> 1;

    const float* __restrict__ B = g_W + (size_t)s * D * D;

    if (tid < 128) aux[tid] = g_b[s * D + n0 + tid];

    auto load_stage = [&](int c, int st) {
        float* bufA = fsm + st * STAGE;
        float* bufB = bufA + A_F;
        #pragma unroll
        for (int it = 0; it < 4; it++) {
            int idx = it * 256 + tid;                  // [0,1024)
            int ra = idx >> 3, ja = idx & 7;           // A: 128 rows x 8 float4
            cp16(smem_u32(bufA + ra * LDA + ja * 4),
                 X + (size_t)(m0 + ra) * D + c * BK + ja * 4);
            int rb = idx >> 5, jb = idx & 31;          // B: 32 rows x 32 float4
            cp16(smem_u32(bufB + rb * LDB + jb * 4),
                 B + (size_t)(c * BK + rb) * D + n0 + jb * 4);
        }
        CP_COMMIT();
    };

    wmma::fragment<wmma::accumulator, 16, 16, 8, float> acc[4][2];
    #pragma unroll
    for (int mt = 0; mt < 4; mt++)
        #pragma unroll
        for (int nt = 0; nt < 2; nt++)
            wmma::fill_fragment(acc[mt][nt], 0.0f);

    load_stage(0, 0);
    load_stage(1, 1);

    for (int c = 0; c < NCH; c++) {
        if (c == NCH - 1) { CP_WAIT(0); } else { CP_WAIT(1); }
        __syncthreads();
        float* sA = fsm + (c & 1) * STAGE;
        float* sB = sA + A_F;

        #pragma unroll
        for (int kk = 0; kk < 4; kk++) {
            wmma::fragment<wmma::matrix_a, 16, 16, 8, wmma::precision::tf32, wmma::row_major> ah[4], al[4];
            wmma::fragment<wmma::matrix_b, 16, 16, 8, wmma::precision::tf32, wmma::row_major> bh[2], bl[2];
            #pragma unroll
            for (int mt = 0; mt < 4; mt++) {
                wmma::load_matrix_sync(ah[mt], sA + (wm * 64 + mt * 16) * LDA + kk * 8, LDA);
                split_frag(ah[mt], al[mt]);
            }
            #pragma unroll
            for (int nt = 0; nt < 2; nt++) {
                wmma::load_matrix_sync(bh[nt], sB + (kk * 8) * LDB + wn * 32 + nt * 16, LDB);
                split_frag(bh[nt], bl[nt]);
            }
            #pragma unroll
            for (int mt = 0; mt < 4; mt++)
                #pragma unroll
                for (int nt = 0; nt < 2; nt++) {
                    wmma::mma_sync(acc[mt][nt], ah[mt], bh[nt], acc[mt][nt]);
                    wmma::mma_sync(acc[mt][nt], ah[mt], bl[nt], acc[mt][nt]);
                    wmma::mma_sync(acc[mt][nt], al[mt], bh[nt], acc[mt][nt]);
                }
        }
        __syncthreads();
        if (c + 2 < NCH) load_stage(c + 2, c & 1);
    }

    // epilogue: bias add, write fp32 tq
    __syncthreads();
    float* scratch = fsm + wid * 512;
    #pragma unroll
    for (int mt = 0; mt < 4; mt++) {
        wmma::store_matrix_sync(scratch,      acc[mt][0], 32, wmma::mem_row_major);
        wmma::store_matrix_sync(scratch + 16, acc[mt][1], 32, wmma::mem_row_major);
        __syncwarp();
        #pragma unroll
        for (int r = 0; r < 16; r++) {
            int row = m0 + wm * 64 + mt * 16 + r;
            float v = scratch[r * 32 + lane] + aux[wn * 32 + lane];
            g_tq[(size_t)(s * NQ + row) * D + n0 + wn * 32 + lane] = v;
        }
        __syncwarp();
    }
}

// -------------- GEMM2: wmma tf32x2 distance kernel (verified core) ----------
__global__ __launch_bounds__(256, 2) void gemm_tf32_dist(const float* __restrict__ P) {
    constexpr int BK  = 32;
    constexpr int NCH = D / BK;        // 16
    constexpr int LDT = 40;
    constexpr int T_F = 128 * LDT;     // 5120
    constexpr int STAGE = 2 * T_F;     // 10240 floats (A then B)

    extern __shared__ float fsm[];
    float* aux = fsm + 2 * STAGE;      // 128 floats (||p||^2)

    const int s  = blockIdx.z;
    const int m0 = blockIdx.y * 128;
    const int n0 = blockIdx.x * 128;
    const int tid = threadIdx.x;
    const int wid = tid >> 5, lane = tid & 31;
    const int wm  = wid & 1, wn = wid >> 1;

    const float* __restrict__ A = g_tq + (size_t)s * NQ * D;

    if (tid < 128) aux[tid] = g_sqp[n0 + tid];

    auto load_stage = [&](int c, int st) {
        float* bufA = fsm + st * STAGE;
        float* bufB = bufA + T_F;
        #pragma unroll
        for (int it = 0; it < 4; it++) {
            int idx = it * 256 + tid;          // [0,1024): 128 rows x 8 float4
            int row = idx >> 3, j = idx & 7;
            cp16(smem_u32(bufA + row * LDT + j * 4),
                 A + (size_t)(m0 + row) * D + c * BK + j * 4);
            cp16(smem_u32(bufB + row * LDT + j * 4),
                 P + (size_t)(n0 + row) * D + c * BK + j * 4);
        }
        CP_COMMIT();
    };

    wmma::fragment<wmma::accumulator, 16, 16, 8, float> acc[4][2];
    #pragma unroll
    for (int mt = 0; mt < 4; mt++)
        #pragma unroll
        for (int nt = 0; nt < 2; nt++)
            wmma::fill_fragment(acc[mt][nt], 0.0f);

    load_stage(0, 0);
    load_stage(1, 1);

    for (int c = 0; c < NCH; c++) {
        if (c == NCH - 1) { CP_WAIT(0); } else { CP_WAIT(1); }
        __syncthreads();
        float* sA = fsm + (c & 1) * STAGE;
        float* sB = sA + T_F;

        #pragma unroll
        for (int kk = 0; kk < 4; kk++) {
            wmma::fragment<wmma::matrix_a, 16, 16, 8, wmma::precision::tf32, wmma::row_major> ah[4], al[4];
            wmma::fragment<wmma::matrix_b, 16, 16, 8, wmma::precision::tf32, wmma::col_major> bh[2], bl[2];
            #pragma unroll
            for (int mt = 0; mt < 4; mt++) {
                wmma::load_matrix_sync(ah[mt], sA + (wm * 64 + mt * 16) * LDT + kk * 8, LDT);
                split_frag(ah[mt], al[mt]);
            }
            #pragma unroll
            for (int nt = 0; nt < 2; nt++) {
                wmma::load_matrix_sync(bh[nt], sB + (wn * 32 + nt * 16) * LDT + kk * 8, LDT);
                split_frag(bh[nt], bl[nt]);
            }
            #pragma unroll
            for (int mt = 0; mt < 4; mt++)
                #pragma unroll
                for (int nt = 0; nt < 2; nt++) {
                    wmma::mma_sync(acc[mt][nt], ah[mt], bh[nt], acc[mt][nt]);
                    wmma::mma_sync(acc[mt][nt], ah[mt], bl[nt], acc[mt][nt]);
                    wmma::mma_sync(acc[mt][nt], al[mt], bh[nt], acc[mt][nt]);
                }
        }
        __syncthreads();
        if (c + 2 < NCH) load_stage(c + 2, c & 1);
    }

    // epilogue: dist = sqrt(q2 + p2 - 2c)
    __syncthreads();
    float* scratch = fsm + wid * 512;
    #pragma unroll
    for (int mt = 0; mt < 4; mt++) {
        wmma::store_matrix_sync(scratch,      acc[mt][0], 32, wmma::mem_row_major);
        wmma::store_matrix_sync(scratch + 16, acc[mt][1], 32, wmma::mem_row_major);
        __syncwarp();
        #pragma unroll
        for (int r = 0; r < 16; r++) {
            int row = m0 + wm * 64 + mt * 16 + r;
            float q2 = g_sqq[s * NQ + row];
            float cr = scratch[r * 32 + lane];
            float p2 = aux[wn * 32 + lane];
            float dv = sqrtf(fmaxf(q2 + p2 - 2.0f * cr, 1e-12f));
            g_dists[(size_t)(s * NQ + row) * NP + n0 + wn * 32 + lane] = dv;
        }
        __syncwarp();
    }
}

// ------------------------------ reduction -----------------------------------
__global__ void reduce_kernel(float* __restrict__ out) {
    size_t i = (size_t)blockIdx.x * blockDim.x + threadIdx.x;
    float v[S];
    float sum = 0.f;
    #pragma unroll
    for (int s = 0; s < S; s++) {
        v[s] = g_dists[(size_t)s * NQ * NP + i];
        sum += v[s];
    }
    float mean = sum * (1.0f / S);
    float m2 = 0.f;
    #pragma unroll
    for (int s = 0; s < S; s++) {
        float d = v[s] - mean;
        m2 = fmaf(d, d, m2);
    }
    out[i] = mean;
    out[(size_t)NQ * NP + i] = sqrtf(m2 * (1.0f / (S - 1)));
}

// ------------------------------ launcher ------------------------------------
extern "C" void kernel_launch(void* const* d_in, const int* in_sizes, int n_in,
                              void* d_out, int out_size) {
    const float* X    = (const float*)d_in[0];
    const float* P    = (const float*)d_in[1];
    const float* wmu  = (const float*)d_in[2];
    const float* wrho = (const float*)d_in[3];
    const float* bmu  = (const float*)d_in[4];
    const float* brho = (const float*)d_in[5];
    float* out = (float*)d_out;

    constexpr int SMEM1 = (2 * (128 * 40 + 32 * 132) + 128) * 4;   // 75264 B
    constexpr int SMEM2 = (2 * (2 * 128 * 40) + 128) * 4;          // 82432 B
    cudaFuncSetAttribute(gemm_tf32_tq,   cudaFuncAttributeMaxDynamicSharedMemorySize, SMEM1);
    cudaFuncSetAttribute(gemm_tf32_dist, cudaFuncAttributeMaxDynamicSharedMemorySize, SMEM2);

    const unsigned key0 = 0u, key1 = 42u;
    unsigned kw0, kw1, kb0, kb1;
    { unsigned x0 = 0u, x1 = 0u; tf2x32(key0, key1, x0, x1); kw0 = x0; kw1 = x1; }
    { unsigned x0 = 0u, x1 = 1u; tf2x32(key0, key1, x0, x1); kb0 = x0; kb1 = x1; }

    gen_w_kernel<<<(S * D * D) / 256, 256>>>(wmu, wrho, kw0, kw1);
    gen_b_kernel<<<(S * D) / 256, 256>>>(bmu, brho, kb0, kb1);
    sqp_kernel<<<NP / 8, 256>>>(P);

    gemm_tf32_tq<<<dim3(D / 128, NQ / 128, S), 256, SMEM1>>>(X);
    sqq_kernel<<<(S * NQ) / 8, 256>>>();

    gemm_tf32_dist<<<dim3(NP / 128, NQ / 128, S), 256, SMEM2>>>(P);

    reduce_kernel<<<(NQ * NP) / 256, 256>>>(out);
}

// round 10
// speedup vs baseline: 1.9703x; 1.9703x over previous
#include <cuda_runtime.h>
#include <mma.h>
#include <cstdint>
#include <cstddef>

using namespace nvcuda;

constexpr int S  = 10;
constexpr int D  = 512;
constexpr int NQ = 4096;
constexpr int NP = 1024;

// ------------------------- scratch (__device__ globals) ---------------------
__device__ float g_W[S * D * D];              // fp32 W [s][d][e]
__device__ float g_b[S * D];
__device__ float g_tq[(size_t)S * NQ * D];
__device__ float g_sqq[S * NQ];
__device__ float g_sqp[NP];
__device__ float g_dists[(size_t)S * NQ * NP];

// ------------------------------ Threefry-2x32 -------------------------------
__host__ __device__ __forceinline__ unsigned rotl32(unsigned x, int d) {
    return (x << d) | (x >> (32 - d));
}
__host__ __device__ __forceinline__ void tf2x32(unsigned k0, unsigned k1,
                                                unsigned &x0, unsigned &x1) {
    unsigned k2 = k0 ^ k1 ^ 0x1BD11BDAu;
    x0 += k0; x1 += k1;
#define TFR(r) { x0 += x1; x1 = rotl32(x1, r) ^ x0; }
    TFR(13) TFR(15) TFR(26) TFR(6)   x0 += k1; x1 += k2 + 1u;
    TFR(17) TFR(29) TFR(16) TFR(24)  x0 += k2; x1 += k0 + 2u;
    TFR(13) TFR(15) TFR(26) TFR(6)   x0 += k0; x1 += k1 + 3u;
    TFR(17) TFR(29) TFR(16) TFR(24)  x0 += k1; x1 += k2 + 4u;
    TFR(13) TFR(15) TFR(26) TFR(6)   x0 += k2; x1 += k0 + 5u;
#undef TFR
}
__device__ __forceinline__ unsigned jax_bits32(unsigned k0, unsigned k1, unsigned i) {
    unsigned x0 = 0u, x1 = i;
    tf2x32(k0, k1, x0, x1);
    return x0 ^ x1;
}
__device__ __forceinline__ float erfinv_xla(float x) {
    float w = -log1pf(-x * x);
    float p;
    if (w < 5.0f) {
        w -= 2.5f;
        p = 2.81022636e-08f;
        p = fmaf(p, w, 3.43273939e-07f);
        p = fmaf(p, w, -3.5233877e-06f);
        p = fmaf(p, w, -4.39150654e-06f);
        p = fmaf(p, w, 0.00021858087f);
        p = fmaf(p, w, -0.00125372503f);
        p = fmaf(p, w, -0.00417768164f);
        p = fmaf(p, w, 0.246640727f);
        p = fmaf(p, w, 1.50140941f);
    } else {
        w = sqrtf(w) - 3.0f;
        p = -0.000200214257f;
        p = fmaf(p, w, 0.000100950558f);
        p = fmaf(p, w, 0.00134934322f);
        p = fmaf(p, w, -0.00367342844f);
        p = fmaf(p, w, 0.00573950773f);
        p = fmaf(p, w, -0.0076224613f);
        p = fmaf(p, w, 0.00943887047f);
        p = fmaf(p, w, 1.00167406f);
        p = fmaf(p, w, 2.83297682f);
    }
    return p * x;
}
__device__ __forceinline__ float bits_to_normal(unsigned bits) {
    float f = __uint_as_float((bits >> 9) | 0x3F800000u) - 1.0f;
    float u = fmaxf(-0.99999994f, f * 2.0f - 0.99999994f);
    return 1.41421356237f * erfinv_xla(u);
}

// ------------------------------ prep kernels --------------------------------
__global__ void gen_w_kernel(const float* __restrict__ wmu,
                             const float* __restrict__ wrho,
                             unsigned k0, unsigned k1) {
    int i = blockIdx.x * blockDim.x + threadIdx.x;
    if (i >= S * D * D) return;
    float eps = bits_to_normal(jax_bits32(k0, k1, (unsigned)i));
    int j = i & (D * D - 1);
    g_W[i] = fmaf(log1pf(expf(wrho[j])), eps, wmu[j]);
}

__global__ void gen_b_kernel(const float* __restrict__ bmu,
                             const float* __restrict__ brho,
                             unsigned k0, unsigned k1) {
    int i = blockIdx.x * blockDim.x + threadIdx.x;
    if (i >= S * D) return;
    float eps = bits_to_normal(jax_bits32(k0, k1, (unsigned)i));
    int j = i & (D - 1);
    g_b[i] = fmaf(log1pf(expf(brho[j])), eps, bmu[j]);
}

__global__ void sqp_kernel(const float* __restrict__ P) {
    int p = blockIdx.x * 8 + (threadIdx.x >> 5);
    int lane = threadIdx.x & 31;
    const float* row = P + (size_t)p * D;
    float s = 0.f;
    for (int e = lane; e < D; e += 32) { float v = row[e]; s = fmaf(v, v, s); }
    #pragma unroll
    for (int o = 16; o; o >>= 1) s += __shfl_xor_sync(0xffffffffu, s, o);
    if (lane == 0) g_sqp[p] = s;
}

__global__ void sqq_kernel() {
    int row = blockIdx.x * 8 + (threadIdx.x >> 5);
    int lane = threadIdx.x & 31;
    const float* r = g_tq + (size_t)row * D;
    float s = 0.f;
    for (int e = lane; e < D; e += 32) { float v = r[e]; s = fmaf(v, v, s); }
    #pragma unroll
    for (int o = 16; o; o >>= 1) s += __shfl_xor_sync(0xffffffffu, s, o);
    if (lane == 0) g_sqq[row] = s;
}

// ------------------------------ async helpers --------------------------------
__device__ __forceinline__ uint32_t smem_u32(const void* p) {
    uint32_t a;
    asm("{ .reg .u64 t; cvta.to.shared.u64 t, %1; cvt.u32.u64 %0, t; }" : "=r"(a) : "l"(p));
    return a;
}
__device__ __forceinline__ void cp16(uint32_t dst, const void* src) {
    asm volatile("cp.async.cg.shared.global [%0], [%1], 16;" :: "r"(dst), "l"(src));
}
#define CP_COMMIT() asm volatile("cp.async.commit_group;" ::: "memory")
#define CP_WAIT(n)  asm volatile("cp.async.wait_group %0;" :: "n"(n) : "memory")

// round fragment elements to tf32 (required by wmma tf32 contract)
template <typename FragT>
__device__ __forceinline__ void round_frag(FragT& f) {
    #pragma unroll
    for (int e = 0; e < f.num_elements; e++)
        f.x[e] = wmma::__float_to_tf32(f.x[e]);
}

// ---------------- GEMM1: wmma tf32 (single term), tq = X @ W_s + b ----------
// 128x128 tile, BK=32, 2-stage cp.async pipeline, 256 threads (8 warps 64x32).
__global__ __launch_bounds__(256, 2) void gemm_tf32_tq(const float* __restrict__ X) {
    constexpr int BK  = 32;
    constexpr int NCH = D / BK;            // 16
    constexpr int LDA = 40;
    constexpr int LDB = 132;
    constexpr int A_F = 128 * LDA;         // 5120
    constexpr int B_F = BK * LDB;          // 4224
    constexpr int STAGE = A_F + B_F;

    extern __shared__ float fsm[];
    float* aux = fsm + 2 * STAGE;

    const int s  = blockIdx.z;
    const int m0 = blockIdx.y * 128;
    const int n0 = blockIdx.x * 128;
    const int tid = threadIdx.x;
    const int wid = tid >> 5, lane = tid & 31;
    const int wm  = wid & 1, wn = wid >> 1;

    const float* __restrict__ B = g_W + (size_t)s * D * D;

    if (tid < 128) aux[tid] = g_b[s * D + n0 + tid];

    auto load_stage = [&](int c, int st) {
        float* bufA = fsm + st * STAGE;
        float* bufB = bufA + A_F;
        #pragma unroll
        for (int it = 0; it < 4; it++) {
            int idx = it * 256 + tid;
            int ra = idx >> 3, ja = idx & 7;
            cp16(smem_u32(bufA + ra * LDA + ja * 4),
                 X + (size_t)(m0 + ra) * D + c * BK + ja * 4);
            int rb = idx >> 5, jb = idx & 31;
            cp16(smem_u32(bufB + rb * LDB + jb * 4),
                 B + (size_t)(c * BK + rb) * D + n0 + jb * 4);
        }
        CP_COMMIT();
    };

    wmma::fragment<wmma::accumulator, 16, 16, 8, float> acc[4][2];
    #pragma unroll
    for (int mt = 0; mt < 4; mt++)
        #pragma unroll
        for (int nt = 0; nt < 2; nt++)
            wmma::fill_fragment(acc[mt][nt], 0.0f);

    load_stage(0, 0);
    load_stage(1, 1);

    for (int c = 0; c < NCH; c++) {
        if (c == NCH - 1) { CP_WAIT(0); } else { CP_WAIT(1); }
        __syncthreads();
        float* sA = fsm + (c & 1) * STAGE;
        float* sB = sA + A_F;

        #pragma unroll
        for (int kk = 0; kk < 4; kk++) {
            wmma::fragment<wmma::matrix_a, 16, 16, 8, wmma::precision::tf32, wmma::row_major> af[4];
            wmma::fragment<wmma::matrix_b, 16, 16, 8, wmma::precision::tf32, wmma::row_major> bf[2];
            #pragma unroll
            for (int mt = 0; mt < 4; mt++) {
                wmma::load_matrix_sync(af[mt], sA + (wm * 64 + mt * 16) * LDA + kk * 8, LDA);
                round_frag(af[mt]);
            }
            #pragma unroll
            for (int nt = 0; nt < 2; nt++) {
                wmma::load_matrix_sync(bf[nt], sB + (kk * 8) * LDB + wn * 32 + nt * 16, LDB);
                round_frag(bf[nt]);
            }
            #pragma unroll
            for (int mt = 0; mt < 4; mt++)
                #pragma unroll
                for (int nt = 0; nt < 2; nt++)
                    wmma::mma_sync(acc[mt][nt], af[mt], bf[nt], acc[mt][nt]);
        }
        __syncthreads();
        if (c + 2 < NCH) load_stage(c + 2, c & 1);
    }

    // epilogue: bias add, write fp32 tq
    __syncthreads();
    float* scratch = fsm + wid * 512;
    #pragma unroll
    for (int mt = 0; mt < 4; mt++) {
        wmma::store_matrix_sync(scratch,      acc[mt][0], 32, wmma::mem_row_major);
        wmma::store_matrix_sync(scratch + 16, acc[mt][1], 32, wmma::mem_row_major);
        __syncwarp();
        #pragma unroll
        for (int r = 0; r < 16; r++) {
            int row = m0 + wm * 64 + mt * 16 + r;
            float v = scratch[r * 32 + lane] + aux[wn * 32 + lane];
            g_tq[(size_t)(s * NQ + row) * D + n0 + wn * 32 + lane] = v;
        }
        __syncwarp();
    }
}

// -------------- GEMM2: wmma tf32 (single term) distance kernel --------------
__global__ __launch_bounds__(256, 2) void gemm_tf32_dist(const float* __restrict__ P) {
    constexpr int BK  = 32;
    constexpr int NCH = D / BK;
    constexpr int LDT = 40;
    constexpr int T_F = 128 * LDT;
    constexpr int STAGE = 2 * T_F;

    extern __shared__ float fsm[];
    float* aux = fsm + 2 * STAGE;

    const int s  = blockIdx.z;
    const int m0 = blockIdx.y * 128;
    const int n0 = blockIdx.x * 128;
    const int tid = threadIdx.x;
    const int wid = tid >> 5, lane = tid & 31;
    const int wm  = wid & 1, wn = wid >> 1;

    const float* __restrict__ A = g_tq + (size_t)s * NQ * D;

    if (tid < 128) aux[tid] = g_sqp[n0 + tid];

    auto load_stage = [&](int c, int st) {
        float* bufA = fsm + st * STAGE;
        float* bufB = bufA + T_F;
        #pragma unroll
        for (int it = 0; it < 4; it++) {
            int idx = it * 256 + tid;
            int row = idx >> 3, j = idx & 7;
            cp16(smem_u32(bufA + row * LDT + j * 4),
                 A + (size_t)(m0 + row) * D + c * BK + j * 4);
            cp16(smem_u32(bufB + row * LDT + j * 4),
                 P + (size_t)(n0 + row) * D + c * BK + j * 4);
        }
        CP_COMMIT();
    };

    wmma::fragment<wmma::accumulator, 16, 16, 8, float> acc[4][2];
    #pragma unroll
    for (int mt = 0; mt < 4; mt++)
        #pragma unroll
        for (int nt = 0; nt < 2; nt++)
            wmma::fill_fragment(acc[mt][nt], 0.0f);

    load_stage(0, 0);
    load_stage(1, 1);

    for (int c = 0; c < NCH; c++) {
        if (c == NCH - 1) { CP_WAIT(0); } else { CP_WAIT(1); }
        __syncthreads();
        float* sA = fsm + (c & 1) * STAGE;
        float* sB = sA + T_F;

        #pragma unroll
        for (int kk = 0; kk < 4; kk++) {
            wmma::fragment<wmma::matrix_a, 16, 16, 8, wmma::precision::tf32, wmma::row_major> af[4];
            wmma::fragment<wmma::matrix_b, 16, 16, 8, wmma::precision::tf32, wmma::col_major> bf[2];
            #pragma unroll
            for (int mt = 0; mt < 4; mt++) {
                wmma::load_matrix_sync(af[mt], sA + (wm * 64 + mt * 16) * LDT + kk * 8, LDT);
                round_frag(af[mt]);
            }
            #pragma unroll
            for (int nt = 0; nt < 2; nt++) {
                wmma::load_matrix_sync(bf[nt], sB + (wn * 32 + nt * 16) * LDT + kk * 8, LDT);
                round_frag(bf[nt]);
            }
            #pragma unroll
            for (int mt = 0; mt < 4; mt++)
                #pragma unroll
                for (int nt = 0; nt < 2; nt++)
                    wmma::mma_sync(acc[mt][nt], af[mt], bf[nt], acc[mt][nt]);
        }
        __syncthreads();
        if (c + 2 < NCH) load_stage(c + 2, c & 1);
    }

    // epilogue: dist = sqrt(q2 + p2 - 2c)
    __syncthreads();
    float* scratch = fsm + wid * 512;
    #pragma unroll
    for (int mt = 0; mt < 4; mt++) {
        wmma::store_matrix_sync(scratch,      acc[mt][0], 32, wmma::mem_row_major);
        wmma::store_matrix_sync(scratch + 16, acc[mt][1], 32, wmma::mem_row_major);
        __syncwarp();
        #pragma unroll
        for (int r = 0; r < 16; r++) {
            int row = m0 + wm * 64 + mt * 16 + r;
            float q2 = g_sqq[s * NQ + row];
            float cr = scratch[r * 32 + lane];
            float p2 = aux[wn * 32 + lane];
            float dv = sqrtf(fmaxf(q2 + p2 - 2.0f * cr, 1e-12f));
            g_dists[(size_t)(s * NQ + row) * NP + n0 + wn * 32 + lane] = dv;
        }
        __syncwarp();
    }
}

// ------------------------------ reduction -----------------------------------
__global__ void reduce_kernel(float* __restrict__ out) {
    size_t i = (size_t)blockIdx.x * blockDim.x + threadIdx.x;
    float v[S];
    float sum = 0.f;
    #pragma unroll
    for (int s = 0; s < S; s++) {
        v[s] = g_dists[(size_t)s * NQ * NP + i];
        sum += v[s];
    }
    float mean = sum * (1.0f / S);
    float m2 = 0.f;
    #pragma unroll
    for (int s = 0; s < S; s++) {
        float d = v[s] - mean;
        m2 = fmaf(d, d, m2);
    }
    out[i] = mean;
    out[(size_t)NQ * NP + i] = sqrtf(m2 * (1.0f / (S - 1)));
}

// ------------------------------ launcher ------------------------------------
extern "C" void kernel_launch(void* const* d_in, const int* in_sizes, int n_in,
                              void* d_out, int out_size) {
    const float* X    = (const float*)d_in[0];
    const float* P    = (const float*)d_in[1];
    const float* wmu  = (const float*)d_in[2];
    const float* wrho = (const float*)d_in[3];
    const float* bmu  = (const float*)d_in[4];
    const float* brho = (const float*)d_in[5];
    float* out = (float*)d_out;

    constexpr int SMEM1 = (2 * (128 * 40 + 32 * 132) + 128) * 4;   // 75264 B
    constexpr int SMEM2 = (2 * (2 * 128 * 40) + 128) * 4;          // 82432 B
    cudaFuncSetAttribute(gemm_tf32_tq,   cudaFuncAttributeMaxDynamicSharedMemorySize, SMEM1);
    cudaFuncSetAttribute(gemm_tf32_dist, cudaFuncAttributeMaxDynamicSharedMemorySize, SMEM2);

    const unsigned key0 = 0u, key1 = 42u;
    unsigned kw0, kw1, kb0, kb1;
    { unsigned x0 = 0u, x1 = 0u; tf2x32(key0, key1, x0, x1); kw0 = x0; kw1 = x1; }
    { unsigned x0 = 0u, x1 = 1u; tf2x32(key0, key1, x0, x1); kb0 = x0; kb1 = x1; }

    gen_w_kernel<<<(S * D * D) / 256, 256>>>(wmu, wrho, kw0, kw1);
    gen_b_kernel<<<(S * D) / 256, 256>>>(bmu, brho, kb0, kb1);
    sqp_kernel<<<NP / 8, 256>>>(P);

    gemm_tf32_tq<<<dim3(D / 128, NQ / 128, S), 256, SMEM1>>>(X);
    sqq_kernel<<<(S * NQ) / 8, 256>>>();

    gemm_tf32_dist<<<dim3(NP / 128, NQ / 128, S), 256, SMEM2>>>(P);

    reduce_kernel<<<(NQ * NP) / 256, 256>>>(out);
}

// round 11
// speedup vs baseline: 2.0572x; 1.0441x over previous
#include <cuda_runtime.h>
#include <mma.h>
#include <cstdint>
#include <cstddef>

using namespace nvcuda;

constexpr int S  = 10;
constexpr int D  = 512;
constexpr int NQ = 4096;
constexpr int NP = 1024;

// ------------------------- scratch (__device__ globals) ---------------------
__device__ float g_W[S * D * D];              // fp32 W [s][d][e]
__device__ float g_b[S * D];
__device__ float g_tq[(size_t)S * NQ * D];
__device__ float g_sqq[S * NQ];
__device__ float g_sqp[NP];
__device__ float g_dists[(size_t)S * NQ * NP];

// ------------------------------ Threefry-2x32 -------------------------------
__host__ __device__ __forceinline__ unsigned rotl32(unsigned x, int d) {
    return (x << d) | (x >> (32 - d));
}
__host__ __device__ __forceinline__ void tf2x32(unsigned k0, unsigned k1,
                                                unsigned &x0, unsigned &x1) {
    unsigned k2 = k0 ^ k1 ^ 0x1BD11BDAu;
    x0 += k0; x1 += k1;
#define TFR(r) { x0 += x1; x1 = rotl32(x1, r) ^ x0; }
    TFR(13) TFR(15) TFR(26) TFR(6)   x0 += k1; x1 += k2 + 1u;
    TFR(17) TFR(29) TFR(16) TFR(24)  x0 += k2; x1 += k0 + 2u;
    TFR(13) TFR(15) TFR(26) TFR(6)   x0 += k0; x1 += k1 + 3u;
    TFR(17) TFR(29) TFR(16) TFR(24)  x0 += k1; x1 += k2 + 4u;
    TFR(13) TFR(15) TFR(26) TFR(6)   x0 += k2; x1 += k0 + 5u;
#undef TFR
}
__device__ __forceinline__ unsigned jax_bits32(unsigned k0, unsigned k1, unsigned i) {
    unsigned x0 = 0u, x1 = i;
    tf2x32(k0, k1, x0, x1);
    return x0 ^ x1;
}
__device__ __forceinline__ float erfinv_xla(float x) {
    float w = -log1pf(-x * x);
    float p;
    if (w < 5.0f) {
        w -= 2.5f;
        p = 2.81022636e-08f;
        p = fmaf(p, w, 3.43273939e-07f);
        p = fmaf(p, w, -3.5233877e-06f);
        p = fmaf(p, w, -4.39150654e-06f);
        p = fmaf(p, w, 0.00021858087f);
        p = fmaf(p, w, -0.00125372503f);
        p = fmaf(p, w, -0.00417768164f);
        p = fmaf(p, w, 0.246640727f);
        p = fmaf(p, w, 1.50140941f);
    } else {
        w = sqrtf(w) - 3.0f;
        p = -0.000200214257f;
        p = fmaf(p, w, 0.000100950558f);
        p = fmaf(p, w, 0.00134934322f);
        p = fmaf(p, w, -0.00367342844f);
        p = fmaf(p, w, 0.00573950773f);
        p = fmaf(p, w, -0.0076224613f);
        p = fmaf(p, w, 0.00943887047f);
        p = fmaf(p, w, 1.00167406f);
        p = fmaf(p, w, 2.83297682f);
    }
    return p * x;
}
__device__ __forceinline__ float bits_to_normal(unsigned bits) {
    float f = __uint_as_float((bits >> 9) | 0x3F800000u) - 1.0f;
    float u = fmaxf(-0.99999994f, f * 2.0f - 0.99999994f);
    return 1.41421356237f * erfinv_xla(u);
}

// ------------------------------ prep kernels --------------------------------
__global__ void gen_w_kernel(const float* __restrict__ wmu,
                             const float* __restrict__ wrho,
                             unsigned k0, unsigned k1) {
    int i = blockIdx.x * blockDim.x + threadIdx.x;
    if (i >= S * D * D) return;
    float eps = bits_to_normal(jax_bits32(k0, k1, (unsigned)i));
    int j = i & (D * D - 1);
    g_W[i] = fmaf(log1pf(expf(wrho[j])), eps, wmu[j]);
}

__global__ void gen_b_kernel(const float* __restrict__ bmu,
                             const float* __restrict__ brho,
                             unsigned k0, unsigned k1) {
    int i = blockIdx.x * blockDim.x + threadIdx.x;
    if (i >= S * D) return;
    float eps = bits_to_normal(jax_bits32(k0, k1, (unsigned)i));
    int j = i & (D - 1);
    g_b[i] = fmaf(log1pf(expf(brho[j])), eps, bmu[j]);
}

__global__ void sqp_kernel(const float* __restrict__ P) {
    int p = blockIdx.x * 8 + (threadIdx.x >> 5);
    int lane = threadIdx.x & 31;
    const float* row = P + (size_t)p * D;
    float s = 0.f;
    for (int e = lane; e < D; e += 32) { float v = row[e]; s = fmaf(v, v, s); }
    #pragma unroll
    for (int o = 16; o; o >>= 1) s += __shfl_xor_sync(0xffffffffu, s, o);
    if (lane == 0) g_sqp[p] = s;
}

__global__ void sqq_kernel() {
    int row = blockIdx.x * 8 + (threadIdx.x >> 5);
    int lane = threadIdx.x & 31;
    const float* r = g_tq + (size_t)row * D;
    float s = 0.f;
    for (int e = lane; e < D; e += 32) { float v = r[e]; s = fmaf(v, v, s); }
    #pragma unroll
    for (int o = 16; o; o >>= 1) s += __shfl_xor_sync(0xffffffffu, s, o);
    if (lane == 0) g_sqq[row] = s;
}

// ------------------------------ async helpers --------------------------------
__device__ __forceinline__ uint32_t smem_u32(const void* p) {
    uint32_t a;
    asm("{ .reg .u64 t; cvta.to.shared.u64 t, %1; cvt.u32.u64 %0, t; }" : "=r"(a) : "l"(p));
    return a;
}
__device__ __forceinline__ void cp16(uint32_t dst, const void* src) {
    asm volatile("cp.async.cg.shared.global [%0], [%1], 16;" :: "r"(dst), "l"(src));
}
#define CP_COMMIT() asm volatile("cp.async.commit_group;" ::: "memory")
#define CP_WAIT(n)  asm volatile("cp.async.wait_group %0;" :: "n"(n) : "memory")

// ---------------- GEMM1: wmma tf32 (single term), tq = X @ W_s + b ----------
// 128x128 tile, BK=32, 2-stage cp.async pipeline, 256 threads (8 warps 64x32).
// NOTE: no explicit f32->tf32 rounding — HMMA reads the tf32 bits of the fp32
// operand registers (truncation), same error order as RN; removes all
// conversion FMA/ALU from the hot loop.
__global__ __launch_bounds__(256, 2) void gemm_tf32_tq(const float* __restrict__ X) {
    constexpr int BK  = 32;
    constexpr int NCH = D / BK;            // 16
    constexpr int LDA = 40;
    constexpr int LDB = 132;
    constexpr int A_F = 128 * LDA;         // 5120
    constexpr int B_F = BK * LDB;          // 4224
    constexpr int STAGE = A_F + B_F;

    extern __shared__ float fsm[];
    float* aux = fsm + 2 * STAGE;

    const int s  = blockIdx.z;
    const int m0 = blockIdx.y * 128;
    const int n0 = blockIdx.x * 128;
    const int tid = threadIdx.x;
    const int wid = tid >> 5, lane = tid & 31;
    const int wm  = wid & 1, wn = wid >> 1;

    const float* __restrict__ B = g_W + (size_t)s * D * D;

    if (tid < 128) aux[tid] = g_b[s * D + n0 + tid];

    auto load_stage = [&](int c, int st) {
        float* bufA = fsm + st * STAGE;
        float* bufB = bufA + A_F;
        #pragma unroll
        for (int it = 0; it < 4; it++) {
            int idx = it * 256 + tid;
            int ra = idx >> 3, ja = idx & 7;
            cp16(smem_u32(bufA + ra * LDA + ja * 4),
                 X + (size_t)(m0 + ra) * D + c * BK + ja * 4);
            int rb = idx >> 5, jb = idx & 31;
            cp16(smem_u32(bufB + rb * LDB + jb * 4),
                 B + (size_t)(c * BK + rb) * D + n0 + jb * 4);
        }
        CP_COMMIT();
    };

    wmma::fragment<wmma::accumulator, 16, 16, 8, float> acc[4][2];
    #pragma unroll
    for (int mt = 0; mt < 4; mt++)
        #pragma unroll
        for (int nt = 0; nt < 2; nt++)
            wmma::fill_fragment(acc[mt][nt], 0.0f);

    load_stage(0, 0);
    load_stage(1, 1);

    for (int c = 0; c < NCH; c++) {
        if (c == NCH - 1) { CP_WAIT(0); } else { CP_WAIT(1); }
        __syncthreads();
        float* sA = fsm + (c & 1) * STAGE;
        float* sB = sA + A_F;

        #pragma unroll
        for (int kk = 0; kk < 4; kk++) {
            wmma::fragment<wmma::matrix_a, 16, 16, 8, wmma::precision::tf32, wmma::row_major> af[4];
            wmma::fragment<wmma::matrix_b, 16, 16, 8, wmma::precision::tf32, wmma::row_major> bf[2];
            #pragma unroll
            for (int mt = 0; mt < 4; mt++)
                wmma::load_matrix_sync(af[mt], sA + (wm * 64 + mt * 16) * LDA + kk * 8, LDA);
            #pragma unroll
            for (int nt = 0; nt < 2; nt++)
                wmma::load_matrix_sync(bf[nt], sB + (kk * 8) * LDB + wn * 32 + nt * 16, LDB);
            #pragma unroll
            for (int mt = 0; mt < 4; mt++)
                #pragma unroll
                for (int nt = 0; nt < 2; nt++)
                    wmma::mma_sync(acc[mt][nt], af[mt], bf[nt], acc[mt][nt]);
        }
        __syncthreads();
        if (c + 2 < NCH) load_stage(c + 2, c & 1);
    }

    // epilogue: bias add, write fp32 tq
    __syncthreads();
    float* scratch = fsm + wid * 512;
    #pragma unroll
    for (int mt = 0; mt < 4; mt++) {
        wmma::store_matrix_sync(scratch,      acc[mt][0], 32, wmma::mem_row_major);
        wmma::store_matrix_sync(scratch + 16, acc[mt][1], 32, wmma::mem_row_major);
        __syncwarp();
        #pragma unroll
        for (int r = 0; r < 16; r++) {
            int row = m0 + wm * 64 + mt * 16 + r;
            float v = scratch[r * 32 + lane] + aux[wn * 32 + lane];
            g_tq[(size_t)(s * NQ + row) * D + n0 + wn * 32 + lane] = v;
        }
        __syncwarp();
    }
}

// -------------- GEMM2: wmma tf32 (single term) distance kernel --------------
__global__ __launch_bounds__(256, 2) void gemm_tf32_dist(const float* __restrict__ P) {
    constexpr int BK  = 32;
    constexpr int NCH = D / BK;
    constexpr int LDT = 40;
    constexpr int T_F = 128 * LDT;
    constexpr int STAGE = 2 * T_F;

    extern __shared__ float fsm[];
    float* aux = fsm + 2 * STAGE;

    const int s  = blockIdx.z;
    const int m0 = blockIdx.y * 128;
    const int n0 = blockIdx.x * 128;
    const int tid = threadIdx.x;
    const int wid = tid >> 5, lane = tid & 31;
    const int wm  = wid & 1, wn = wid >> 1;

    const float* __restrict__ A = g_tq + (size_t)s * NQ * D;

    if (tid < 128) aux[tid] = g_sqp[n0 + tid];

    auto load_stage = [&](int c, int st) {
        float* bufA = fsm + st * STAGE;
        float* bufB = bufA + T_F;
        #pragma unroll
        for (int it = 0; it < 4; it++) {
            int idx = it * 256 + tid;
            int row = idx >> 3, j = idx & 7;
            cp16(smem_u32(bufA + row * LDT + j * 4),
                 A + (size_t)(m0 + row) * D + c * BK + j * 4);
            cp16(smem_u32(bufB + row * LDT + j * 4),
                 P + (size_t)(n0 + row) * D + c * BK + j * 4);
        }
        CP_COMMIT();
    };

    wmma::fragment<wmma::accumulator, 16, 16, 8, float> acc[4][2];
    #pragma unroll
    for (int mt = 0; mt < 4; mt++)
        #pragma unroll
        for (int nt = 0; nt < 2; nt++)
            wmma::fill_fragment(acc[mt][nt], 0.0f);

    load_stage(0, 0);
    load_stage(1, 1);

    for (int c = 0; c < NCH; c++) {
        if (c == NCH - 1) { CP_WAIT(0); } else { CP_WAIT(1); }
        __syncthreads();
        float* sA = fsm + (c & 1) * STAGE;
        float* sB = sA + T_F;

        #pragma unroll
        for (int kk = 0; kk < 4; kk++) {
            wmma::fragment<wmma::matrix_a, 16, 16, 8, wmma::precision::tf32, wmma::row_major> af[4];
            wmma::fragment<wmma::matrix_b, 16, 16, 8, wmma::precision::tf32, wmma::col_major> bf[2];
            #pragma unroll
            for (int mt = 0; mt < 4; mt++)
                wmma::load_matrix_sync(af[mt], sA + (wm * 64 + mt * 16) * LDT + kk * 8, LDT);
            #pragma unroll
            for (int nt = 0; nt < 2; nt++)
                wmma::load_matrix_sync(bf[nt], sB + (wn * 32 + nt * 16) * LDT + kk * 8, LDT);
            #pragma unroll
            for (int mt = 0; mt < 4; mt++)
                #pragma unroll
                for (int nt = 0; nt < 2; nt++)
                    wmma::mma_sync(acc[mt][nt], af[mt], bf[nt], acc[mt][nt]);
        }
        __syncthreads();
        if (c + 2 < NCH) load_stage(c + 2, c & 1);
    }

    // epilogue: dist = sqrt(q2 + p2 - 2c)
    __syncthreads();
    float* scratch = fsm + wid * 512;
    #pragma unroll
    for (int mt = 0; mt < 4; mt++) {
        wmma::store_matrix_sync(scratch,      acc[mt][0], 32, wmma::mem_row_major);
        wmma::store_matrix_sync(scratch + 16, acc[mt][1], 32, wmma::mem_row_major);
        __syncwarp();
        #pragma unroll
        for (int r = 0; r < 16; r++) {
            int row = m0 + wm * 64 + mt * 16 + r;
            float q2 = g_sqq[s * NQ + row];
            float cr = scratch[r * 32 + lane];
            float p2 = aux[wn * 32 + lane];
            float dv = sqrtf(fmaxf(q2 + p2 - 2.0f * cr, 1e-12f));
            g_dists[(size_t)(s * NQ + row) * NP + n0 + wn * 32 + lane] = dv;
        }
        __syncwarp();
    }
}

// ------------------------------ reduction (float4) ---------------------------
__global__ void reduce_kernel(float* __restrict__ out) {
    size_t i4 = (size_t)blockIdx.x * blockDim.x + threadIdx.x;   // over NQ*NP/4
    size_t i = i4 * 4;
    float4 v[S];
    float4 sum = make_float4(0.f, 0.f, 0.f, 0.f);
    #pragma unroll
    for (int s = 0; s < S; s++) {
        v[s] = *(const float4*)(g_dists + (size_t)s * NQ * NP + i);
        sum.x += v[s].x; sum.y += v[s].y; sum.z += v[s].z; sum.w += v[s].w;
    }
    float4 mean = make_float4(sum.x * 0.1f, sum.y * 0.1f, sum.z * 0.1f, sum.w * 0.1f);
    float4 m2 = make_float4(0.f, 0.f, 0.f, 0.f);
    #pragma unroll
    for (int s = 0; s < S; s++) {
        float dx = v[s].x - mean.x, dy = v[s].y - mean.y;
        float dz = v[s].z - mean.z, dw = v[s].w - mean.w;
        m2.x = fmaf(dx, dx, m2.x); m2.y = fmaf(dy, dy, m2.y);
        m2.z = fmaf(dz, dz, m2.z); m2.w = fmaf(dw, dw, m2.w);
    }
    *(float4*)(out + i) = mean;
    float4 sd;
    sd.x = sqrtf(m2.x * (1.0f / 9.0f)); sd.y = sqrtf(m2.y * (1.0f / 9.0f));
    sd.z = sqrtf(m2.z * (1.0f / 9.0f)); sd.w = sqrtf(m2.w * (1.0f / 9.0f));
    *(float4*)(out + (size_t)NQ * NP + i) = sd;
}

// ------------------------------ launcher ------------------------------------
extern "C" void kernel_launch(void* const* d_in, const int* in_sizes, int n_in,
                              void* d_out, int out_size) {
    const float* X    = (const float*)d_in[0];
    const float* P    = (const float*)d_in[1];
    const float* wmu  = (const float*)d_in[2];
    const float* wrho = (const float*)d_in[3];
    const float* bmu  = (const float*)d_in[4];
    const float* brho = (const float*)d_in[5];
    float* out = (float*)d_out;

    constexpr int SMEM1 = (2 * (128 * 40 + 32 * 132) + 128) * 4;   // 75264 B
    constexpr int SMEM2 = (2 * (2 * 128 * 40) + 128) * 4;          // 82432 B
    cudaFuncSetAttribute(gemm_tf32_tq,   cudaFuncAttributeMaxDynamicSharedMemorySize, SMEM1);
    cudaFuncSetAttribute(gemm_tf32_dist, cudaFuncAttributeMaxDynamicSharedMemorySize, SMEM2);

    const unsigned key0 = 0u, key1 = 42u;
    unsigned kw0, kw1, kb0, kb1;
    { unsigned x0 = 0u, x1 = 0u; tf2x32(key0, key1, x0, x1); kw0 = x0; kw1 = x1; }
    { unsigned x0 = 0u, x1 = 1u; tf2x32(key0, key1, x0, x1); kb0 = x0; kb1 = x1; }

    gen_w_kernel<<<(S * D * D) / 256, 256>>>(wmu, wrho, kw0, kw1);
    gen_b_kernel<<<(S * D) / 256, 256>>>(bmu, brho, kb0, kb1);
    sqp_kernel<<<NP / 8, 256>>>(P);

    gemm_tf32_tq<<<dim3(D / 128, NQ / 128, S), 256, SMEM1>>>(X);
    sqq_kernel<<<(S * NQ) / 8, 256>>>();

    gemm_tf32_dist<<<dim3(NP / 128, NQ / 128, S), 256, SMEM2>>>(P);

    reduce_kernel<<<(NQ * NP / 4) / 256, 256>>>(out);
}